// round 15
// baseline (speedup 1.0000x reference)
#include <cuda_runtime.h>
#include <cuda_fp16.h>
#include <cstdint>

#define NPTS 100000
#define BSZ  8
#define CIMG 512
#define CPT  256
#define IMH  48
#define IMW  160
#define HW   (IMH*IMW)      /* 7680  */
#define NPIX (BSZ*HW)       /* 61440 */
#define NTILES 960          /* 64-pixel GEMM tiles: 8 batches x 120 */
#define TPB 120             /* tiles per batch */

#define MASK_BLOCKS ((NPTS + 255) / 256)        /* 391 */
#define CONVW_BLOCKS ((CPT * CIMG + 255) / 256) /* 512 */

// Scratch (device globals; no allocation in kernel_launch)
__device__ __half g_Wh[CPT * CIMG];                  // align_w in fp16, row-major (256,512)
__device__ __half g_pix[(size_t)NPIX * CPT];         // channel-last projected pixels, fp16
__device__ int    g_tileflags[NTILES];               // zeroed by compact_kernel each run
__device__ int    g_tilelist[NTILES];
__device__ int    g_tilecount;

// ---------------------------------------------------------------------------
// Shared projection helper (must match fuse_kernel semantics exactly)
// ---------------------------------------------------------------------------
__device__ __forceinline__ void project_point(
    int n, const float* __restrict__ centers,
    const float* __restrict__ P2, const float* __restrict__ R0,
    const float* __restrict__ Tr, const int* __restrict__ bidx,
    int& b_out, bool& valid, int& xi0, int& yi0,
    float& wx0, float& wx1, float& wy0, float& wy1)
{
    const int b = bidx[n];
    b_out = b;
    const float px = centers[n * 3 + 0];
    const float py = centers[n * 3 + 1];
    const float pz = centers[n * 3 + 2];
    const float* tr = Tr + b * 16;
    const float* r0 = R0 + b * 16;
    const float* p2 = P2 + b * 12;

    float cam[4], rect[4], im[3];
    #pragma unroll
    for (int i = 0; i < 4; i++)
        cam[i] = tr[i*4+0]*px + tr[i*4+1]*py + tr[i*4+2]*pz + tr[i*4+3];
    #pragma unroll
    for (int i = 0; i < 4; i++)
        rect[i] = r0[i*4+0]*cam[0] + r0[i*4+1]*cam[1] + r0[i*4+2]*cam[2] + r0[i*4+3]*cam[3];
    #pragma unroll
    for (int i = 0; i < 3; i++)
        im[i] = p2[i*4+0]*rect[0] + p2[i*4+1]*rect[1] + p2[i*4+2]*rect[2] + p2[i*4+3]*rect[3];

    const float zc    = im[2];
    const float depth = fmaxf(zc, 1e-5f);
    const float u     = im[0] / depth;
    const float v     = im[1] / depth;
    valid = (zc > 0.f) && (u >= 0.f) && (u < (float)IMW) && (v >= 0.f) && (v < (float)IMH);

    const float x0f = floorf(u), y0f = floorf(v);
    wx1 = u - x0f; wx0 = 1.f - wx1;
    wy1 = v - y0f; wy0 = 1.f - wy1;
    xi0 = (int)x0f; yi0 = (int)y0f;
}

// ---------------------------------------------------------------------------
// Kernel A (merged): blocks [0, MASK_BLOCKS) mark active GEMM tiles;
//                    blocks [MASK_BLOCKS, +CONVW_BLOCKS) convert align_w.
// ---------------------------------------------------------------------------
__global__ void prep_kernel(const float* __restrict__ centers,
                            const float* __restrict__ P2,
                            const float* __restrict__ R0,
                            const float* __restrict__ Tr,
                            const int*   __restrict__ bidx,
                            const float* __restrict__ W) {
    const int tid = threadIdx.x;
    if ((int)blockIdx.x >= MASK_BLOCKS) {
        int i = ((int)blockIdx.x - MASK_BLOCKS) * 256 + tid;
        if (i < CPT * CIMG) g_Wh[i] = __float2half_rn(W[i]);
        return;
    }
    __shared__ unsigned char sf[NTILES];
    for (int i = tid; i < NTILES; i += 256) sf[i] = 0;
    __syncthreads();

    const int n = blockIdx.x * 256 + tid;
    if (n < NPTS) {
        int b, xi0, yi0; bool valid; float wx0, wx1, wy0, wy1;
        project_point(n, centers, P2, R0, Tr, bidx, b, valid, xi0, yi0, wx0, wx1, wy0, wy1);
        #pragma unroll
        for (int k = 0; k < 4; k++) {
            int xc = min(max(xi0 + (k & 1), 0), IMW - 1);
            int yc = min(max(yi0 + (k >> 1), 0), IMH - 1);
            int p  = yc * IMW + xc;
            sf[b * TPB + (p >> 6)] = 1;
        }
    }
    __syncthreads();
    for (int i = tid; i < NTILES; i += 256)
        if (sf[i]) g_tileflags[i] = 1;   // idempotent plain store; flags pre-zeroed
}

// ---------------------------------------------------------------------------
// Kernel B: compact active tiles into list + count, reset flags for next run
// ---------------------------------------------------------------------------
__global__ void compact_kernel() {
    __shared__ int cnt;
    const int tid = threadIdx.x;
    if (tid == 0) cnt = 0;
    __syncthreads();
    if (tid < NTILES && g_tileflags[tid]) {
        int p = atomicAdd(&cnt, 1);
        g_tilelist[p] = tid;
        g_tileflags[tid] = 0;            // ready for next graph replay
    }
    __syncthreads();
    if (tid == 0) g_tilecount = cnt;
}

// ---------------------------------------------------------------------------
// Kernel 1: activity-masked GEMM over active 64-pixel tiles only.
//   cp.async 3-stage, BM=64 x BN=256, occ=2, convert-ahead Ah, x4 B-ldmatrix.
// ---------------------------------------------------------------------------
#define BM 64
#define BN 256
#define BK 32
#define STAGES 3

#define A_STAGE_F     (BK * BM)
#define B_ROW_H       (BK + 8)
#define B_STAGE_H     (BN * B_ROW_H)
#define AH_ROW_H      (BM + 8)
#define AH_STAGE_H    (BK * AH_ROW_H)
#define SMEM_TOTAL (STAGES * A_STAGE_F * 4 + STAGES * B_STAGE_H * 2 + 2 * AH_STAGE_H * 2)

__device__ __forceinline__ void cp16(void* s, const void* g) {
    uint32_t sa = (uint32_t)__cvta_generic_to_shared(s);
    asm volatile("cp.async.cg.shared.global [%0], [%1], 16;" :: "r"(sa), "l"(g));
}

__global__ __launch_bounds__(256, 2)
void gemm_pix_kernel(const float* __restrict__ img) {
    if ((int)blockIdx.x >= g_tilecount) return;
    const int tile = g_tilelist[blockIdx.x];
    const int b  = tile / TPB;
    const int p0 = (tile % TPB) * BM;

    extern __shared__ char smem_raw[];
    float*  Af = reinterpret_cast<float*>(smem_raw);
    __half* Bs = reinterpret_cast<__half*>(smem_raw + STAGES * A_STAGE_F * 4);
    __half* Ah = reinterpret_cast<__half*>(smem_raw + STAGES * A_STAGE_F * 4
                                           + STAGES * B_STAGE_H * 2);

    const float* gA = img + (size_t)b * CIMG * HW;

    const int tid  = threadIdx.x;
    const int lane = tid & 31;
    const int warp = tid >> 5;
    const int wm   = warp & 1;
    const int wn   = warp >> 1;

    float acc[2][8][4];
    #pragma unroll
    for (int i = 0; i < 2; i++)
        #pragma unroll
        for (int j = 0; j < 8; j++)
            #pragma unroll
            for (int k = 0; k < 4; k++) acc[i][j][k] = 0.f;

    int ak_[2], am_[2];
    #pragma unroll
    for (int i = 0; i < 2; i++) {
        int idx = tid + i * 256;
        ak_[i] = idx >> 4;
        am_[i] = (idx & 15) << 2;
    }

    #pragma unroll
    for (int s = 0; s < STAGES; s++) {
        const int kt = s * BK;
        #pragma unroll
        for (int i = 0; i < 2; i++)
            cp16(&Af[s * A_STAGE_F + ak_[i] * BM + am_[i]],
                 gA + (size_t)(kt + ak_[i]) * HW + p0 + am_[i]);
        #pragma unroll
        for (int i = 0; i < 4; i++) {
            int idx = tid + i * 256;
            int n = idx >> 2, kc = (idx & 3) << 3;
            cp16(&Bs[s * B_STAGE_H + n * B_ROW_H + kc],
                 &g_Wh[n * CIMG + kt + kc]);
        }
        asm volatile("cp.async.commit_group;");
    }

    asm volatile("cp.async.wait_group %0;" :: "n"(STAGES - 1));
    __syncthreads();
    #pragma unroll
    for (int i = 0; i < 2; i++) {
        float4 v = *reinterpret_cast<const float4*>(&Af[ak_[i] * BM + am_[i]]);
        __half2* dst = reinterpret_cast<__half2*>(&Ah[ak_[i] * AH_ROW_H + am_[i]]);
        dst[0] = __floats2half2_rn(v.x, v.y);
        dst[1] = __floats2half2_rn(v.z, v.w);
    }

    const int NT = CIMG / BK;   // 16
    for (int t = 0; t < NT; t++) {
        const int slot = t % STAGES;
        asm volatile("cp.async.wait_group %0;" :: "n"(1));
        __syncthreads();

        if (t + 1 < NT) {
            const int ns = (t + 1) % STAGES;
            const int na = (t + 1) & 1;
            #pragma unroll
            for (int i = 0; i < 2; i++) {
                float4 v = *reinterpret_cast<const float4*>(
                    &Af[ns * A_STAGE_F + ak_[i] * BM + am_[i]]);
                __half2* dst = reinterpret_cast<__half2*>(
                    &Ah[na * AH_STAGE_H + ak_[i] * AH_ROW_H + am_[i]]);
                dst[0] = __floats2half2_rn(v.x, v.y);
                dst[1] = __floats2half2_rn(v.z, v.w);
            }
        }

        const int ab = (t & 1) * AH_STAGE_H;
        #pragma unroll
        for (int ks = 0; ks < BK; ks += 16) {
            uint32_t af[2][4];
            uint32_t bfr[8][2];
            {
                int jj = lane >> 3, r = lane & 7;
                int m_off = (jj & 1) * 8, k_off = (jj >> 1) * 8;
                #pragma unroll
                for (int mt = 0; mt < 2; mt++) {
                    uint32_t addr = (uint32_t)__cvta_generic_to_shared(
                        &Ah[ab + (ks + k_off + r) * AH_ROW_H + wm * 32 + mt * 16 + m_off]);
                    asm volatile("ldmatrix.sync.aligned.m8n8.x4.trans.shared.b16 {%0,%1,%2,%3}, [%4];"
                                 : "=r"(af[mt][0]), "=r"(af[mt][1]), "=r"(af[mt][2]), "=r"(af[mt][3])
                                 : "r"(addr));
                }
                #pragma unroll
                for (int p = 0; p < 4; p++) {
                    uint32_t addr = (uint32_t)__cvta_generic_to_shared(
                        &Bs[slot * B_STAGE_H
                            + (wn * 64 + (p * 2 + (jj >> 1)) * 8 + r) * B_ROW_H
                            + ks + (jj & 1) * 8]);
                    asm volatile("ldmatrix.sync.aligned.m8n8.x4.shared.b16 {%0,%1,%2,%3}, [%4];"
                                 : "=r"(bfr[2*p][0]), "=r"(bfr[2*p][1]),
                                   "=r"(bfr[2*p+1][0]), "=r"(bfr[2*p+1][1])
                                 : "r"(addr));
                }
            }
            #pragma unroll
            for (int mt = 0; mt < 2; mt++)
                #pragma unroll
                for (int nt = 0; nt < 8; nt++) {
                    asm volatile("mma.sync.aligned.m16n8k16.row.col.f32.f16.f16.f32 "
                                 "{%0,%1,%2,%3}, {%4,%5,%6,%7}, {%8,%9}, {%0,%1,%2,%3};"
                                 : "+f"(acc[mt][nt][0]), "+f"(acc[mt][nt][1]),
                                   "+f"(acc[mt][nt][2]), "+f"(acc[mt][nt][3])
                                 : "r"(af[mt][0]), "r"(af[mt][1]), "r"(af[mt][2]), "r"(af[mt][3]),
                                   "r"(bfr[nt][0]), "r"(bfr[nt][1]));
                }
        }
        __syncthreads();

        if (t + STAGES < NT) {
            const int kt = (t + STAGES) * BK;
            #pragma unroll
            for (int i = 0; i < 2; i++)
                cp16(&Af[slot * A_STAGE_F + ak_[i] * BM + am_[i]],
                     gA + (size_t)(kt + ak_[i]) * HW + p0 + am_[i]);
            #pragma unroll
            for (int i = 0; i < 4; i++) {
                int idx = tid + i * 256;
                int n = idx >> 2, kc = (idx & 3) << 3;
                cp16(&Bs[slot * B_STAGE_H + n * B_ROW_H + kc],
                     &g_Wh[n * CIMG + kt + kc]);
            }
        }
        asm volatile("cp.async.commit_group;");
    }

    const int mrow = lane >> 2;
    const int ncol = (lane & 3) * 2;
    #pragma unroll
    for (int mt = 0; mt < 2; mt++) {
        #pragma unroll
        for (int nt = 0; nt < 8; nt++) {
            int m = wm * 32 + mt * 16 + mrow;
            int n = wn * 64 + nt * 8 + ncol;
            size_t base = ((size_t)(b * HW + p0 + m)) * CPT + n;
            *reinterpret_cast<__half2*>(&g_pix[base]) =
                __floats2half2_rn(acc[mt][nt][0], acc[mt][nt][1]);
            *reinterpret_cast<__half2*>(&g_pix[base + 8 * CPT]) =
                __floats2half2_rn(acc[mt][nt][2], acc[mt][nt][3]);
        }
    }
}

// ---------------------------------------------------------------------------
// Kernel 2: per-point projection + bilinear combine. FOUR points per warp:
//   16 batched pix corner loads + 8 pf float4 in flight, 8 channels/lane.
// ---------------------------------------------------------------------------
#define PTS_PER_WARP 4

__global__ void fuse_kernel(const float* __restrict__ pf,
                            const float* __restrict__ centers,
                            const float* __restrict__ P2,
                            const float* __restrict__ R0,
                            const float* __restrict__ Tr,
                            const float* __restrict__ bias,
                            const int*   __restrict__ bidx,
                            float* __restrict__ out) {
    const int gw   = (blockIdx.x * blockDim.x + threadIdx.x) >> 5;
    const int lane = threadIdx.x & 31;
    const int n0   = gw * PTS_PER_WARP;
    if (n0 >= NPTS) return;           // NPTS % 4 == 0 -> full groups

    const int c = lane * 8;
    float4 bv0 = *reinterpret_cast<const float4*>(bias + c);
    float4 bv1 = *reinterpret_cast<const float4*>(bias + c + 4);

    float    wgt[PTS_PER_WARP][4];
    uint32_t off[PTS_PER_WARP][4];    // element offsets into g_pix (fits 32-bit)

    #pragma unroll
    for (int pidx = 0; pidx < PTS_PER_WARP; pidx++) {
        const int n = n0 + pidx;
        int b, xi0, yi0; bool valid; float wx0, wx1, wy0, wy1;
        project_point(n, centers, P2, R0, Tr, bidx, b, valid, xi0, yi0, wx0, wx1, wy0, wy1);
        const float cw[4] = {wx0 * wy0, wx1 * wy0, wx0 * wy1, wx1 * wy1};
        #pragma unroll
        for (int k = 0; k < 4; k++) {
            int xi = xi0 + (k & 1);
            int yi = yi0 + (k >> 1);
            bool inb = (xi >= 0) && (xi <= IMW - 1) && (yi >= 0) && (yi <= IMH - 1);
            wgt[pidx][k] = (valid && inb) ? cw[k] : 0.f;
            int xc = min(max(xi, 0), IMW - 1);
            int yc = min(max(yi, 0), IMH - 1);
            off[pidx][k] = (uint32_t)((b * IMH + yc) * IMW + xc) * CPT;
        }
    }

    // Batched loads: 16 pix corners + 8 pf float4 in flight
    uint4 raw[PTS_PER_WARP][4];
    #pragma unroll
    for (int pidx = 0; pidx < PTS_PER_WARP; pidx++)
        #pragma unroll
        for (int k = 0; k < 4; k++)
            raw[pidx][k] = *reinterpret_cast<const uint4*>(g_pix + off[pidx][k] + c);

    float4 pfv[PTS_PER_WARP][2];
    #pragma unroll
    for (int pidx = 0; pidx < PTS_PER_WARP; pidx++) {
        const float* pfrow = pf + (size_t)(n0 + pidx) * CPT + c;
        pfv[pidx][0] = *reinterpret_cast<const float4*>(pfrow);
        pfv[pidx][1] = *reinterpret_cast<const float4*>(pfrow + 4);
    }

    #pragma unroll
    for (int pidx = 0; pidx < PTS_PER_WARP; pidx++) {
        float a[8];
        #pragma unroll
        for (int j = 0; j < 8; j++) a[j] = 0.f;
        #pragma unroll
        for (int k = 0; k < 4; k++) {
            const float w = wgt[pidx][k];
            const __half2* h = reinterpret_cast<const __half2*>(&raw[pidx][k]);
            #pragma unroll
            for (int j = 0; j < 4; j++) {
                float2 f = __half22float2(h[j]);
                a[2*j]   = fmaf(w, f.x, a[2*j]);
                a[2*j+1] = fmaf(w, f.y, a[2*j+1]);
            }
        }
        float* orow = out + (size_t)(n0 + pidx) * CPT + c;
        float4 o0, o1;
        o0.x = pfv[pidx][0].x + (a[0] + bv0.x);
        o0.y = pfv[pidx][0].y + (a[1] + bv0.y);
        o0.z = pfv[pidx][0].z + (a[2] + bv0.z);
        o0.w = pfv[pidx][0].w + (a[3] + bv0.w);
        o1.x = pfv[pidx][1].x + (a[4] + bv1.x);
        o1.y = pfv[pidx][1].y + (a[5] + bv1.y);
        o1.z = pfv[pidx][1].z + (a[6] + bv1.z);
        o1.w = pfv[pidx][1].w + (a[7] + bv1.w);
        *reinterpret_cast<float4*>(orow)     = o0;
        *reinterpret_cast<float4*>(orow + 4) = o1;
    }
}

// ---------------------------------------------------------------------------
// Launch: prep(convW|mask) -> compact -> masked GEMM -> fuse
// ---------------------------------------------------------------------------
extern "C" void kernel_launch(void* const* d_in, const int* in_sizes, int n_in,
                              void* d_out, int out_size) {
    const float* point_feat = (const float*)d_in[0];
    const float* centers    = (const float*)d_in[1];
    const float* img_feat   = (const float*)d_in[2];
    const float* P2         = (const float*)d_in[3];
    const float* R0         = (const float*)d_in[4];
    const float* Tr         = (const float*)d_in[5];
    const float* align_w    = (const float*)d_in[6];
    const float* align_b    = (const float*)d_in[7];
    const int*   bidx       = (const int*)d_in[8];
    float* out = (float*)d_out;

    cudaFuncSetAttribute(gemm_pix_kernel,
                         cudaFuncAttributeMaxDynamicSharedMemorySize, SMEM_TOTAL);

    prep_kernel<<<MASK_BLOCKS + CONVW_BLOCKS, 256>>>(centers, P2, R0, Tr, bidx, align_w);
    compact_kernel<<<1, 1024>>>();
    gemm_pix_kernel<<<NTILES, 256, SMEM_TOTAL>>>(img_feat);
    fuse_kernel<<<(NPTS / PTS_PER_WARP + 7) / 8, 256>>>(point_feat, centers, P2, R0, Tr,
                                                        align_b, bidx, out);
}